// round 12
// baseline (speedup 1.0000x reference)
#include <cuda_runtime.h>

#define FULLMASK 0xffffffffu
#define NMO_   40
#define ROWS_  16
#define CSTR   12     // floats per stored MO column; column-major smem
#define CPB    32     // configs per block (128 thr = 64 pairs = 32 cfg x 2 spins)
#define TPB    128

// Pair-cooperative Slater determinants via HOUSEHOLDER QR (2 lanes per 8x8
// matrix, 4 rows/lane). QR needs NO pivoting: rows never move, the active set
// at step k is statically i>=k (pure predication), so the entire ALU-heavy
// pivot machinery of the LU versions (keys, maxes, select-trees, parity)
// disappears. det(A) = (-1)^7 * prod(alpha_k) * R_77; each reflection has
// det -1; a zero column gives alpha=0 -> det=0, so the sign is always right.
__global__ __launch_bounds__(TPB, 10)
void slater_det_kernel(const float* __restrict__ mo,
                       const int*   __restrict__ cup,
                       const int*   __restrict__ cdown,
                       float*       __restrict__ out,
                       int nconf)
{
    __shared__ __align__(16) float mo_sh[2 * NMO_ * CSTR];  // 960 floats
    __shared__ float sh_det[2 * CPB];

    const int b  = blockIdx.y;
    const int c0 = blockIdx.x * CPB;
    const int t  = threadIdx.x;

    // Stage column-major: mo_sh[(s*40+col)*12 + row8] = mo[b, s*8+row8, col]
    {
        const float* src = mo + (size_t)b * (ROWS_ * NMO_);
        #pragma unroll
        for (int idx = t; idx < ROWS_ * NMO_; idx += TPB) {
            const int e   = idx / NMO_;
            const int col = idx % NMO_;
            mo_sh[((e >> 3) * NMO_ + col) * CSTR + (e & 7)] = src[idx];
        }
    }
    __syncthreads();

    const int pairid = t >> 1;            // 0..63
    const int par    = t & 1;             // lane in pair; my rows = par*4 + r
    const int s      = pairid >> 5;       // spin channel
    const int c      = c0 + (pairid & (CPB - 1));

    const int*   cw   = ((s == 0) ? cup : cdown) + c * 8;
    const float* base = mo_sh + s * NMO_ * CSTR + par * 4;  // 16B-aligned

    // Gather: smem column = 8 contiguous rows; my 4 rows = one LDS.128/column.
    float a[4][8];
    {
        int4 ci = __ldg((const int4*)cw);
        const int c4[4] = {ci.x, ci.y, ci.z, ci.w};
        #pragma unroll
        for (int j = 0; j < 4; ++j) {
            const float4 p = *reinterpret_cast<const float4*>(base + c4[j] * CSTR);
            a[0][j] = p.x; a[1][j] = p.y; a[2][j] = p.z; a[3][j] = p.w;
        }
        ci = __ldg((const int4*)cw + 1);
        const int c8[4] = {ci.x, ci.y, ci.z, ci.w};
        #pragma unroll
        for (int j = 0; j < 4; ++j) {
            const float4 p = *reinterpret_cast<const float4*>(base + c8[j] * CSTR);
            a[0][4 + j] = p.x; a[1][4 + j] = p.y; a[2][4 + j] = p.z; a[3][4 + j] = p.w;
        }
    }

    const int par4 = par * 4;   // my global row offset
    float det = 1.0f;

    #pragma unroll
    for (int k = 0; k < 7; ++k) {
        // ||x||^2 over the active part (global rows i >= k) of column k.
        // (par4 + r >= k) is constant or par-dependent per (k, r): pure predication.
        float ss = 0.0f;
        #pragma unroll
        for (int r = 0; r < 4; ++r)
            if (par4 + r >= k) ss = fmaf(a[r][k], a[r][k], ss);
        ss += __shfl_xor_sync(FULLMASK, ss, 1, 2);

        // Diagonal entry x_k lives on lane (k>>2), register (k&3) — static.
        const float xk = __shfl_sync(FULLMASK, a[k & 3][k], k >> 2, 2);

        const float nrm   = (ss > 0.0f) ? ss * __frsqrt_rn(ss) : 0.0f;
        const float alpha = (xk >= 0.0f) ? -nrm : nrm;   // avoid cancellation
        det *= alpha;                                    // R_kk = alpha

        // v = x - alpha*e_k, stored in place in column k (owner lane only).
        if (par == (k >> 2)) a[k & 3][k] = xk - alpha;

        // v'v = ||x||^2 + alpha^2 - 2*alpha*x_k  (no cancellation by sign choice)
        const float vv   = fmaf(alpha, alpha - 2.0f * xk, ss);
        const float beta = (vv > 0.0f) ? 2.0f * __frcp_rn(vv) : 0.0f;

        // Apply H = I - beta*v*v' to the trailing columns.
        #pragma unroll
        for (int j = k + 1; j < 8; ++j) {
            float w = 0.0f;
            #pragma unroll
            for (int r = 0; r < 4; ++r)
                if (par4 + r >= k) w = fmaf(a[r][k], a[r][j], w);
            w += __shfl_xor_sync(FULLMASK, w, 1, 2);
            const float tv = beta * w;
            #pragma unroll
            for (int r = 0; r < 4; ++r)
                if (par4 + r >= k) a[r][j] = fmaf(-tv, a[r][k], a[r][j]);
        }
    }

    // R_77 = final a[7][7] (lane 1, reg 3); det(Q) = (-1)^7.
    const float a77 = __shfl_sync(FULLMASK, a[3][7], 1, 2);
    det *= -a77;

    if (par == 0) sh_det[pairid] = det;
    __syncthreads();

    // Combine spins; coalesced 128B store per block.
    if (t < CPB)
        out[(size_t)b * nconf + c0 + t] = sh_det[t] * sh_det[CPB + t];
}

extern "C" void kernel_launch(void* const* d_in, const int* in_sizes, int n_in,
                              void* d_out, int out_size)
{
    const float* mo    = (const float*)d_in[0];  // (B, 16, 40) f32
    const int*   cup   = (const int*)  d_in[1];  // (C, 8) i32
    const int*   cdown = (const int*)  d_in[2];  // (C, 8) i32
    float*       out   = (float*)d_out;          // (B, C) f32

    const int B = in_sizes[0] / (ROWS_ * NMO_);
    const int C = in_sizes[1] / 8;

    dim3 grid(C / CPB, B);
    slater_det_kernel<<<grid, TPB>>>(mo, cup, cdown, out, C);
}

// round 13
// speedup vs baseline: 1.2630x; 1.2630x over previous
#include <cuda_runtime.h>

#define FULLMASK 0xffffffffu
#define NMO_   40
#define ROWS_  16
#define CSTR   12     // floats per stored MO column; column-major smem
#define CPB    32     // configs per block (128 thr = 64 pairs = 32 cfg x 2 spins)
#define TPB    128

// Raw MUFU.RCP (rel err ~2^-22): one instruction vs __frcp_rn's refinement
// sequence. Winner-row exact-zeroing does not depend on rcp accuracy.
__device__ __forceinline__ float frcp_fast(float x) {
    float r;
    asm("rcp.approx.f32 %0, %1;" : "=f"(r) : "f"(x));
    return r;
}

// 4-way register select keyed directly on loc bits 1,2.
__device__ __forceinline__ float sel4loc(float x0, float x1, float x2, float x3, int loc) {
    const float lo = (loc & 2) ? x1 : x0;
    const float hi = (loc & 2) ? x3 : x2;
    return (loc & 4) ? hi : lo;
}

// Pair-cooperative Slater determinants: 2 lanes per 8x8 matrix, 4 rows/lane.
//  - pivoted LU for 6 steps; terminal 2x2 Schur block solved in closed form
//    (saves the two most expensive pivot headers)
//  - retired rows exactly zero (winner multiplier forced to 1.0 -> bit-exact
//    self-annihilation), so pivot keys need no retirement masks
//  - permutation parity via running seen-mask popcount; the 2x2 tail adds its
//    two inversion terms with the same formula
__global__ __launch_bounds__(TPB, 10)
void slater_det_kernel(const float* __restrict__ mo,
                       const int*   __restrict__ cup,
                       const int*   __restrict__ cdown,
                       float*       __restrict__ out,
                       int nconf)
{
    __shared__ __align__(16) float mo_sh[2 * NMO_ * CSTR];  // 960 floats
    __shared__ float sh_det[2 * CPB];

    const int b  = blockIdx.y;
    const int c0 = blockIdx.x * CPB;
    const int t  = threadIdx.x;

    // Stage column-major: mo_sh[(s*40+col)*12 + row8] = mo[b, s*8+row8, col]
    {
        const float* src = mo + (size_t)b * (ROWS_ * NMO_);
        #pragma unroll
        for (int idx = t; idx < ROWS_ * NMO_; idx += TPB) {
            const int e   = idx / NMO_;
            const int col = idx % NMO_;
            mo_sh[((e >> 3) * NMO_ + col) * CSTR + (e & 7)] = src[idx];
        }
    }
    __syncthreads();

    const int pairid = t >> 1;            // 0..63
    const int par    = t & 1;             // lane in pair; my rows = par*4 + r
    const int s      = pairid >> 5;       // spin channel
    const int c      = c0 + (pairid & (CPB - 1));

    const int*   cw   = ((s == 0) ? cup : cdown) + c * 8;
    const float* base = mo_sh + s * NMO_ * CSTR + par * 4;  // 16B-aligned

    // Gather: smem column = 8 contiguous rows; my 4 rows = one LDS.128/column.
    float a[4][8];
    {
        int4 ci = __ldg((const int4*)cw);
        const int c4[4] = {ci.x, ci.y, ci.z, ci.w};
        #pragma unroll
        for (int j = 0; j < 4; ++j) {
            const float4 p = *reinterpret_cast<const float4*>(base + c4[j] * CSTR);
            a[0][j] = p.x; a[1][j] = p.y; a[2][j] = p.z; a[3][j] = p.w;
        }
        ci = __ldg((const int4*)cw + 1);
        const int c8[4] = {ci.x, ci.y, ci.z, ci.w};
        #pragma unroll
        for (int j = 0; j < 4; ++j) {
            const float4 p = *reinterpret_cast<const float4*>(base + c8[j] * CSTR);
            a[0][4 + j] = p.x; a[1][4 + j] = p.y; a[2][4 + j] = p.z; a[3][4 + j] = p.w;
        }
    }

    // Row tags: loc = (row<<1)|par, distinct across the 8 global rows.
    const int l0 = par, l1 = par | 2, l2 = par | 4, l3 = par | 6;

    float detA = 1.0f, detB = 1.0f;   // split pivot products (break FMUL chain)
    int   seen = 0;                   // bitmask of winning locs so far
    int   cnt  = 0;                   // inversion count of the loc sequence

    #pragma unroll
    for (int k = 0; k < 6; ++k) {
        // Key: |a| with low-3 mantissa bits replaced by the tag.
        // Retired rows are exactly 0 -> key = tag only -> never beats live rows.
        const unsigned k0 = (__float_as_uint(a[0][k]) & 0x7FFFFFF8u) | (unsigned)l0;
        const unsigned k1 = (__float_as_uint(a[1][k]) & 0x7FFFFFF8u) | (unsigned)l1;
        const unsigned k2 = (__float_as_uint(a[2][k]) & 0x7FFFFFF8u) | (unsigned)l2;
        const unsigned k3 = (__float_as_uint(a[3][k]) & 0x7FFFFFF8u) | (unsigned)l3;
        unsigned key = (k0 > k1) ? k0 : k1;
        key = (k2 > key) ? k2 : key;
        key = (k3 > key) ? k3 : key;
        {
            const unsigned o = __shfl_xor_sync(FULLMASK, key, 1, 2);
            key = (o > key) ? o : key;
        }
        const int loc = (int)(key & 7u);

        // Parity: inversions against already-retired locs.
        cnt  += __popc((unsigned)seen >> loc);
        seen |= 1 << loc;

        // Pivot value broadcast: srcLane = loc (taken mod width 2).
        const float cand = sel4loc(a[0][k], a[1][k], a[2][k], a[3][k], loc);
        const float prk  = __shfl_sync(FULLMASK, cand, loc, 2);
        if (k & 1) detB *= prk; else detA *= prk;

        // Multipliers; winner's forced to exactly 1.0 so its row
        // self-annihilates bit-exactly and stays 0 for all later steps.
        const float inv = frcp_fast(prk);
        const float f0 = (loc == l0) ? 1.0f : a[0][k] * inv;
        const float f1 = (loc == l1) ? 1.0f : a[1][k] * inv;
        const float f2 = (loc == l2) ? 1.0f : a[2][k] * inv;
        const float f3 = (loc == l3) ? 1.0f : a[3][k] * inv;

        #pragma unroll
        for (int j = k + 1; j < 8; ++j) {
            const float cj  = sel4loc(a[0][j], a[1][j], a[2][j], a[3][j], loc);
            const float prj = __shfl_sync(FULLMASK, cj, loc, 2);
            a[0][j] = fmaf(-f0, prj, a[0][j]);
            a[1][j] = fmaf(-f1, prj, a[1][j]);
            a[2][j] = fmaf(-f2, prj, a[2][j]);
            a[3][j] = fmaf(-f3, prj, a[3][j]);
        }
    }

    // Terminal 2x2 Schur block in closed form (replaces pivot steps 6, 7).
    float det;
    {
        const unsigned rem = (~(unsigned)seen) & 0xFFu;   // two live locs
        const int locA = __ffs(rem) - 1;
        const int locB = __ffs(rem & (rem - 1)) - 1;      // locA < locB

        // Parity as if pivot slot 6 = locA, slot 7 = locB.
        cnt += __popc((unsigned)seen >> locA);
        cnt += __popc(((unsigned)seen | (1u << locA)) >> locB);

        // Extract the four entries of the 2x2 block.
        const float a6A = __shfl_sync(FULLMASK,
            sel4loc(a[0][6], a[1][6], a[2][6], a[3][6], locA), locA, 2);
        const float a7A = __shfl_sync(FULLMASK,
            sel4loc(a[0][7], a[1][7], a[2][7], a[3][7], locA), locA, 2);
        const float a6B = __shfl_sync(FULLMASK,
            sel4loc(a[0][6], a[1][6], a[2][6], a[3][6], locB), locB, 2);
        const float a7B = __shfl_sync(FULLMASK,
            sel4loc(a[0][7], a[1][7], a[2][7], a[3][7], locB), locB, 2);

        const float det2 = fmaf(a6A, a7B, -a7A * a6B);
        det = detA * detB * det2;
        det = (cnt & 1) ? -det : det;
    }

    if (par == 0) sh_det[pairid] = det;
    __syncthreads();

    // Combine spins; coalesced 128B store per block.
    if (t < CPB)
        out[(size_t)b * nconf + c0 + t] = sh_det[t] * sh_det[CPB + t];
}

extern "C" void kernel_launch(void* const* d_in, const int* in_sizes, int n_in,
                              void* d_out, int out_size)
{
    const float* mo    = (const float*)d_in[0];  // (B, 16, 40) f32
    const int*   cup   = (const int*)  d_in[1];  // (C, 8) i32
    const int*   cdown = (const int*)  d_in[2];  // (C, 8) i32
    float*       out   = (float*)d_out;          // (B, C) f32

    const int B = in_sizes[0] / (ROWS_ * NMO_);
    const int C = in_sizes[1] / 8;

    dim3 grid(C / CPB, B);
    slater_det_kernel<<<grid, TPB>>>(mo, cup, cdown, out, C);
}

// round 14
// speedup vs baseline: 1.5710x; 1.2439x over previous
#include <cuda_runtime.h>

#define FULLMASK 0xffffffffu
#define NMO_   40
#define ROWS_  16
#define CSTR   12     // floats per stored MO column; column-major smem
#define CPB    32     // configs per block (128 thr = 64 pairs = 32 cfg x 2 spins)
#define TPB    128
#define PIV_TAU 1e-4f // min-|pivot| threshold that triggers the pivoted redo

__device__ __forceinline__ float frcp_fast(float x) {
    float r;
    asm("rcp.approx.f32 %0, %1;" : "=f"(r) : "f"(x));
    return r;
}

// 4-way register select keyed directly on loc bits 1,2 (redo path only).
__device__ __forceinline__ float sel4loc(float x0, float x1, float x2, float x3, int loc) {
    const float lo = (loc & 2) ? x1 : x0;
    const float hi = (loc & 2) ? x3 : x2;
    return (loc & 4) ? hi : lo;
}

// Gather the 8x8 Slater matrix (4 rows per lane) from column-major smem.
__device__ __forceinline__ void gather8(const int* __restrict__ cw,
                                        const float* __restrict__ base,
                                        float a[4][8]) {
    int4 ci = __ldg((const int4*)cw);
    const int c4[4] = {ci.x, ci.y, ci.z, ci.w};
    #pragma unroll
    for (int j = 0; j < 4; ++j) {
        const float4 p = *reinterpret_cast<const float4*>(base + c4[j] * CSTR);
        a[0][j] = p.x; a[1][j] = p.y; a[2][j] = p.z; a[3][j] = p.w;
    }
    ci = __ldg((const int4*)cw + 1);
    const int c8[4] = {ci.x, ci.y, ci.z, ci.w};
    #pragma unroll
    for (int j = 0; j < 4; ++j) {
        const float4 p = *reinterpret_cast<const float4*>(base + c8[j] * CSTR);
        a[0][4 + j] = p.x; a[1][4 + j] = p.y; a[2][4 + j] = p.z; a[3][4 + j] = p.w;
    }
}

// Pair-cooperative Slater determinants: 2 lanes per 8x8 matrix, 4 rows/lane.
// FAST PATH: UNPIVOTED LU. The pivot row at step k sits at a STATIC location
// (lane k>>2, register k&3), so its broadcast is a bare shfl -- no keys, no
// maxes, no select trees, no parity. Updates are unconditional on all 4 rows:
// rows already retired (or the pivot row itself) get corrupted but are never
// read after their own step. min|pivot| is tracked; if any det in the warp
// sees a pivot below PIV_TAU, the whole warp re-gathers and re-runs the
// proven pivoted LU (warp-uniform branch, ~1% of warps).
__global__ __launch_bounds__(TPB, 10)
void slater_det_kernel(const float* __restrict__ mo,
                       const int*   __restrict__ cup,
                       const int*   __restrict__ cdown,
                       float*       __restrict__ out,
                       int nconf)
{
    __shared__ __align__(16) float mo_sh[2 * NMO_ * CSTR];  // 960 floats
    __shared__ float sh_det[2 * CPB];

    const int b  = blockIdx.y;
    const int c0 = blockIdx.x * CPB;
    const int t  = threadIdx.x;

    // Stage column-major: mo_sh[(s*40+col)*12 + row8] = mo[b, s*8+row8, col]
    {
        const float* src = mo + (size_t)b * (ROWS_ * NMO_);
        #pragma unroll
        for (int idx = t; idx < ROWS_ * NMO_; idx += TPB) {
            const int e   = idx / NMO_;
            const int col = idx % NMO_;
            mo_sh[((e >> 3) * NMO_ + col) * CSTR + (e & 7)] = src[idx];
        }
    }
    __syncthreads();

    const int pairid = t >> 1;            // 0..63
    const int par    = t & 1;             // lane in pair; my rows = par*4 + r
    const int s      = pairid >> 5;       // spin channel
    const int c      = c0 + (pairid & (CPB - 1));

    const int*   cw   = ((s == 0) ? cup : cdown) + c * 8;
    const float* base = mo_sh + s * NMO_ * CSTR + par * 4;  // 16B-aligned

    float a[4][8];
    gather8(cw, base, a);

    // ---------- fast path: unpivoted LU ----------
    float detA = 1.0f, detB = 1.0f;
    float minp = 1e30f;

    #pragma unroll
    for (int k = 0; k < 7; ++k) {
        // Pivot row is static: lane k>>2, register k&3.
        const float prk = __shfl_sync(FULLMASK, a[k & 3][k], k >> 2, 2);
        minp = fminf(minp, fabsf(prk));
        if (k & 1) detB *= prk; else detA *= prk;

        const float inv = frcp_fast(prk);
        const float f0 = a[0][k] * inv;
        const float f1 = a[1][k] * inv;
        const float f2 = a[2][k] * inv;
        const float f3 = a[3][k] * inv;

        #pragma unroll
        for (int j = k + 1; j < 8; ++j) {
            const float prj = __shfl_sync(FULLMASK, a[k & 3][j], k >> 2, 2);
            a[0][j] = fmaf(-f0, prj, a[0][j]);
            a[1][j] = fmaf(-f1, prj, a[1][j]);
            a[2][j] = fmaf(-f2, prj, a[2][j]);
            a[3][j] = fmaf(-f3, prj, a[3][j]);
        }
    }
    const float u77 = __shfl_sync(FULLMASK, a[3][7], 1, 2);
    float det = detA * (detB * u77);

    // ---------- guarded rare path: pivoted LU redo ----------
    if (__any_sync(FULLMASK, minp < PIV_TAU)) {
        gather8(cw, base, a);   // re-gather the original matrix

        const int l0 = par, l1 = par | 2, l2 = par | 4, l3 = par | 6;
        det = 1.0f;
        int seen = 0, cnt = 0;

        #pragma unroll
        for (int k = 0; k < 8; ++k) {
            const unsigned k0 = (__float_as_uint(a[0][k]) & 0x7FFFFFF8u) | (unsigned)l0;
            const unsigned k1 = (__float_as_uint(a[1][k]) & 0x7FFFFFF8u) | (unsigned)l1;
            const unsigned k2 = (__float_as_uint(a[2][k]) & 0x7FFFFFF8u) | (unsigned)l2;
            const unsigned k3 = (__float_as_uint(a[3][k]) & 0x7FFFFFF8u) | (unsigned)l3;
            unsigned key = (k0 > k1) ? k0 : k1;
            key = (k2 > key) ? k2 : key;
            key = (k3 > key) ? k3 : key;
            {
                const unsigned o = __shfl_xor_sync(FULLMASK, key, 1, 2);
                key = (o > key) ? o : key;
            }
            const int loc = (int)(key & 7u);

            cnt  += __popc((unsigned)seen >> loc);
            seen |= 1 << loc;

            const float cand = sel4loc(a[0][k], a[1][k], a[2][k], a[3][k], loc);
            const float prk  = __shfl_sync(FULLMASK, cand, loc, 2);
            det *= prk;

            const float inv = __frcp_rn(prk);
            const float f0 = (loc == l0) ? 1.0f : a[0][k] * inv;
            const float f1 = (loc == l1) ? 1.0f : a[1][k] * inv;
            const float f2 = (loc == l2) ? 1.0f : a[2][k] * inv;
            const float f3 = (loc == l3) ? 1.0f : a[3][k] * inv;

            #pragma unroll
            for (int j = k + 1; j < 8; ++j) {
                const float cj  = sel4loc(a[0][j], a[1][j], a[2][j], a[3][j], loc);
                const float prj = __shfl_sync(FULLMASK, cj, loc, 2);
                a[0][j] = fmaf(-f0, prj, a[0][j]);
                a[1][j] = fmaf(-f1, prj, a[1][j]);
                a[2][j] = fmaf(-f2, prj, a[2][j]);
                a[3][j] = fmaf(-f3, prj, a[3][j]);
            }
        }
        det = (cnt & 1) ? -det : det;
    }

    if (par == 0) sh_det[pairid] = det;
    __syncthreads();

    // Combine spins; coalesced 128B store per block.
    if (t < CPB)
        out[(size_t)b * nconf + c0 + t] = sh_det[t] * sh_det[CPB + t];
}

extern "C" void kernel_launch(void* const* d_in, const int* in_sizes, int n_in,
                              void* d_out, int out_size)
{
    const float* mo    = (const float*)d_in[0];  // (B, 16, 40) f32
    const int*   cup   = (const int*)  d_in[1];  // (C, 8) i32
    const int*   cdown = (const int*)  d_in[2];  // (C, 8) i32
    float*       out   = (float*)d_out;          // (B, C) f32

    const int B = in_sizes[0] / (ROWS_ * NMO_);
    const int C = in_sizes[1] / 8;

    dim3 grid(C / CPB, B);
    slater_det_kernel<<<grid, TPB>>>(mo, cup, cdown, out, C);
}

// round 15
// speedup vs baseline: 1.5816x; 1.0067x over previous
#include <cuda_runtime.h>

#define NMO_   40
#define ROWS_  16
#define CSTR   12     // floats per stored MO column (48B, 16B-aligned, good bank spread)
#define CPB    64     // configs per block (128 thr = 64 cfg x 2 spins)
#define TPB    128
#define PIV_TAU 1e-4f

__device__ __forceinline__ float frcp_fast(float x) {
    float r;
    asm("rcp.approx.f32 %0, %1;" : "=f"(r) : "f"(x));
    return r;
}

// One thread per 8x8 Slater determinant — UNPIVOTED STREAMING LU, no shuffles.
// Phase 1: factor the left 4-column panel (static unrolled; 32 floats live),
//          keep only the 22 L-multipliers.
// Phase 2: stream columns 4..7 one at a time: load, forward-apply L (and the
//          accumulated step-4..6 multipliers), capture the pivot, discard.
// Peak live state ~48 floats -> register-resident (the spill wall that forced
// the old pair-split kernels sat at ~64+ live floats).
// Tiny-pivot guard: rare per-thread redo in fp64 with partial pivoting on a
// dynamically-indexed LOCAL array (costs the hot path zero registers).
__global__ __launch_bounds__(TPB, 8)
void slater_det_kernel(const float* __restrict__ mo,
                       const int*   __restrict__ cup,
                       const int*   __restrict__ cdown,
                       float*       __restrict__ out,
                       int nconf)
{
    __shared__ __align__(16) float mo_sh[2 * NMO_ * CSTR];  // 960 floats
    __shared__ float sh_det[2 * CPB];

    const int b  = blockIdx.y;
    const int c0 = blockIdx.x * CPB;
    const int t  = threadIdx.x;

    // Stage column-major: mo_sh[(s*40+col)*12 + row8] = mo[b, s*8+row8, col]
    {
        const float* src = mo + (size_t)b * (ROWS_ * NMO_);
        #pragma unroll
        for (int idx = t; idx < ROWS_ * NMO_; idx += TPB) {
            const int e   = idx / NMO_;
            const int col = idx % NMO_;
            mo_sh[((e >> 3) * NMO_ + col) * CSTR + (e & 7)] = src[idx];
        }
    }
    __syncthreads();

    const int s  = t >> 6;                // spin channel
    const int cl = t & (CPB - 1);         // local config
    const int c  = c0 + cl;

    const int*   cw   = ((s == 0) ? cup : cdown) + c * 8;
    const float* base = mo_sh + s * NMO_ * CSTR;

    float detA = 1.0f, detB = 1.0f;
    float minp = 1e30f;

    // ---- Phase 1: gather + factor columns 0..3 (P[j][i] = elem(row i, col j)) ----
    float P[4][8];
    {
        const int4 ci = __ldg((const int4*)cw);
        const int c4[4] = {ci.x, ci.y, ci.z, ci.w};
        #pragma unroll
        for (int j = 0; j < 4; ++j) {
            const float4 lo = *reinterpret_cast<const float4*>(base + c4[j] * CSTR);
            const float4 hi = *reinterpret_cast<const float4*>(base + c4[j] * CSTR + 4);
            P[j][0] = lo.x; P[j][1] = lo.y; P[j][2] = lo.z; P[j][3] = lo.w;
            P[j][4] = hi.x; P[j][5] = hi.y; P[j][6] = hi.z; P[j][7] = hi.w;
        }
    }
    #pragma unroll
    for (int k = 0; k < 4; ++k) {
        const float piv = P[k][k];
        minp = fminf(minp, fabsf(piv));
        if (k & 1) detB *= piv; else detA *= piv;
        const float inv = frcp_fast(piv);
        #pragma unroll
        for (int i = k + 1; i < 8; ++i) P[k][i] *= inv;        // L[i][k]
        #pragma unroll
        for (int j = k + 1; j < 4; ++j)
            #pragma unroll
            for (int i = k + 1; i < 8; ++i)
                P[j][i] = fmaf(-P[k][i], P[j][k], P[j][i]);
    }
    // Live from phase 1: only the L entries P[k][i], i > k.

    // ---- Phase 2: stream columns 4..7 ----
    float m45 = 0.f, m46 = 0.f, m47 = 0.f,    // step-4 multipliers
          m56 = 0.f, m57 = 0.f,               // step-5
          m67 = 0.f;                          // step-6
    const int4 ci2 = __ldg((const int4*)cw + 1);
    const int c8[4] = {ci2.x, ci2.y, ci2.z, ci2.w};

    #pragma unroll
    for (int j = 4; j < 8; ++j) {
        float cv[8];
        {
            const float4 lo = *reinterpret_cast<const float4*>(base + c8[j - 4] * CSTR);
            const float4 hi = *reinterpret_cast<const float4*>(base + c8[j - 4] * CSTR + 4);
            cv[0] = lo.x; cv[1] = lo.y; cv[2] = lo.z; cv[3] = lo.w;
            cv[4] = hi.x; cv[5] = hi.y; cv[6] = hi.z; cv[7] = hi.w;
        }
        // forward-apply panel-1 eliminations
        #pragma unroll
        for (int k = 0; k < 4; ++k)
            #pragma unroll
            for (int i = k + 1; i < 8; ++i)
                cv[i] = fmaf(-P[k][i], cv[k], cv[i]);
        // forward-apply step 4..j-1 multipliers
        if (j > 4) { cv[5] = fmaf(-m45, cv[4], cv[5]);
                     cv[6] = fmaf(-m46, cv[4], cv[6]);
                     cv[7] = fmaf(-m47, cv[4], cv[7]); }
        if (j > 5) { cv[6] = fmaf(-m56, cv[5], cv[6]);
                     cv[7] = fmaf(-m57, cv[5], cv[7]); }
        if (j > 6) { cv[7] = fmaf(-m67, cv[6], cv[7]); }

        const float piv = cv[j];
        minp = fminf(minp, fabsf(piv));
        if (j & 1) detB *= piv; else detA *= piv;

        if (j < 7) {
            const float inv = frcp_fast(piv);
            if (j == 4) { m45 = cv[5] * inv; m46 = cv[6] * inv; m47 = cv[7] * inv; }
            if (j == 5) { m56 = cv[6] * inv; m57 = cv[7] * inv; }
            if (j == 6) { m67 = cv[7] * inv; }
        }
    }

    float det = detA * detB;

    // ---- rare path: fp64 pivoted LU on a local array (dynamic indexing ->
    //      local memory; zero register cost to the hot path) ----
    if (minp < PIV_TAU) {
        double m[64];
        #pragma unroll 1
        for (int j = 0; j < 8; ++j) {
            const int col = cw[j];
            #pragma unroll 1
            for (int i = 0; i < 8; ++i)
                m[i * 8 + j] = (double)base[col * CSTR + i];
        }
        double dd = 1.0;
        #pragma unroll 1
        for (int k = 0; k < 8; ++k) {
            int p = k;
            double mx = fabs(m[k * 8 + k]);
            for (int i = k + 1; i < 8; ++i) {
                const double v = fabs(m[i * 8 + k]);
                if (v > mx) { mx = v; p = i; }
            }
            if (p != k) {
                dd = -dd;
                for (int j2 = k; j2 < 8; ++j2) {
                    const double tmp = m[k * 8 + j2];
                    m[k * 8 + j2] = m[p * 8 + j2];
                    m[p * 8 + j2] = tmp;
                }
            }
            const double piv = m[k * 8 + k];
            dd *= piv;
            const double iv = 1.0 / piv;
            for (int i = k + 1; i < 8; ++i) {
                const double f = m[i * 8 + k] * iv;
                for (int j2 = k + 1; j2 < 8; ++j2)
                    m[i * 8 + j2] -= f * m[k * 8 + j2];
            }
        }
        det = (float)dd;
    }

    sh_det[t] = det;
    __syncthreads();

    // Combine spins; coalesced 256B store per block.
    if (t < CPB)
        out[(size_t)b * nconf + c0 + t] = sh_det[t] * sh_det[CPB + t];
}

extern "C" void kernel_launch(void* const* d_in, const int* in_sizes, int n_in,
                              void* d_out, int out_size)
{
    const float* mo    = (const float*)d_in[0];  // (B, 16, 40) f32
    const int*   cup   = (const int*)  d_in[1];  // (C, 8) i32
    const int*   cdown = (const int*)  d_in[2];  // (C, 8) i32
    float*       out   = (float*)d_out;          // (B, C) f32

    const int B = in_sizes[0] / (ROWS_ * NMO_);
    const int C = in_sizes[1] / 8;

    dim3 grid(C / CPB, B);
    slater_det_kernel<<<grid, TPB>>>(mo, cup, cdown, out, C);
}